// round 7
// baseline (speedup 1.0000x reference)
#include <cuda_runtime.h>
#include <cstdint>

#define NPTS   16384
#define NBINS  256
#define ZMIN   (-6.0f)
#define DZ     (12.0f / 256.0f)
#define INV_DZ (256.0f / 12.0f)
#define GRID   128
#define TPB    256

// Zero-initialized at load; last-finishing block resets for next graph replay.
__device__ int      g_hist[2][NBINS];
__device__ int      g_cursor[2][NBINS];
__device__ float4   g_sorted[2][NPTS];   // (-2x,-2y,-2z,|p|^2), z-bin order
__device__ float    g_sum;
__device__ unsigned g_done;
__device__ unsigned g_bar_cnt;
__device__ unsigned g_bar_gen;

__device__ __forceinline__ int zbin(float z) {
    int b = (int)floorf((z - ZMIN) * INV_DZ);
    return max(0, min(NBINS - 1, b));
}

// ---- L2-coherent sync primitives ------------------------------------------
__device__ __forceinline__ unsigned ld_acq(unsigned* p) {
    unsigned v;
    asm volatile("ld.acquire.gpu.global.u32 %0, [%1];" : "=r"(v) : "l"(p) : "memory");
    return v;
}
__device__ __forceinline__ void st_rel(unsigned* p, unsigned v) {
    asm volatile("st.release.gpu.global.u32 [%0], %1;" :: "l"(p), "r"(v) : "memory");
}
__device__ __forceinline__ unsigned atom_add_rel(unsigned* p, unsigned v) {
    unsigned o;
    asm volatile("atom.add.release.gpu.global.u32 %0, [%1], %2;"
                 : "=r"(o) : "l"(p), "r"(v) : "memory");
    return o;
}
__device__ __forceinline__ unsigned atom_add_acqrel(unsigned* p, unsigned v) {
    unsigned o;
    asm volatile("atom.add.acq_rel.gpu.global.u32 %0, [%1], %2;"
                 : "=r"(o) : "l"(p), "r"(v) : "memory");
    return o;
}

// Grid barrier. GRID=128 <= 148 SMs -> all CTAs co-resident in wave 1.
__device__ __forceinline__ void grid_barrier() {
    __syncthreads();
    if (threadIdx.x == 0) {
        __threadfence();
        unsigned gen = ld_acq(&g_bar_gen);
        if (atom_add_rel(&g_bar_cnt, 1u) == GRID - 1) {
            g_bar_cnt = 0;
            st_rel(&g_bar_gen, gen + 1);
        } else {
            while (ld_acq(&g_bar_gen) == gen) __nanosleep(32);
        }
    }
    __syncthreads();
}

// ---- scan one z-bin of targets --------------------------------------------
__device__ __forceinline__ void scan_range(const float4* __restrict__ T4,
                                           int jb, int je,
                                           float sx, float sy, float sz,
                                           float& m) {
    float ma = 3.4e38f, mb = 3.4e38f;
    int j = jb;
    for (; j + 1 < je; j += 2) {
        float4 ta = T4[j];
        float4 tb = T4[j + 1];
        float da = fmaf(sx, ta.x, ta.w);
        float db = fmaf(sx, tb.x, tb.w);
        da = fmaf(sy, ta.y, da);
        db = fmaf(sy, tb.y, db);
        da = fmaf(sz, ta.z, da);
        db = fmaf(sz, tb.z, db);
        ma = fminf(ma, da);
        mb = fminf(mb, db);
    }
    if (j < je) {
        float4 ta = T4[j];
        float da = fmaf(sx, ta.x, ta.w);
        da = fmaf(sy, ta.y, da);
        da = fmaf(sz, ta.z, da);
        ma = fminf(ma, da);
    }
    m = fminf(m, fminf(ma, mb));
}

__global__ void __launch_bounds__(TPB, 1) chamfer_fused(
    const float* __restrict__ pred, const float* __restrict__ tgt,
    float* __restrict__ out)
{
    __shared__ int   sh_scan[2][NBINS];
    __shared__ int   sh_bs[2][NBINS + 1];
    __shared__ float red[TPB];

    const int tid = threadIdx.x;            // TPB == NBINS == 256

    // ---- Phase 1: one point per thread -> global histogram -----------------
    const int gidx = blockIdx.x * TPB + tid;     // 0..32767
    const int pdir = gidx >> 14;
    const int pi   = gidx & (NPTS - 1);
    const float* __restrict__ P = pdir ? tgt : pred;
    const float px = P[3 * pi + 0];
    const float py = P[3 * pi + 1];
    const float pz = P[3 * pi + 2];
    const int  pbin = zbin(pz);
    atomicAdd(&g_hist[pdir][pbin], 1);

    grid_barrier();      // histogram complete everywhere

    // ---- Phase 2: per-CTA redundant scan of the 512-int histogram ----------
    {
        int v0 = g_hist[0][tid];             // cheap: 512 ints from L2
        int v1 = g_hist[1][tid];
        sh_scan[0][tid] = v0;
        sh_scan[1][tid] = v1;
        __syncthreads();
        for (int off = 1; off < NBINS; off <<= 1) {
            int a0 = (tid >= off) ? sh_scan[0][tid - off] : 0;
            int a1 = (tid >= off) ? sh_scan[1][tid - off] : 0;
            __syncthreads();
            sh_scan[0][tid] += a0;
            sh_scan[1][tid] += a1;
            __syncthreads();
        }
        sh_bs[0][tid] = sh_scan[0][tid] - v0;    // exclusive prefix
        sh_bs[1][tid] = sh_scan[1][tid] - v1;
        if (tid == 0) { sh_bs[0][NBINS] = NPTS; sh_bs[1][NBINS] = NPTS; }
        __syncthreads();
    }

    // ---- Phase 2b: scatter this thread's point into bin order --------------
    {
        const int pos = sh_bs[pdir][pbin] + atomicAdd(&g_cursor[pdir][pbin], 1);
        g_sorted[pdir][pos] = make_float4(-2.0f * px, -2.0f * py, -2.0f * pz,
                                          px * px + py * py + pz * pz);
    }

    grid_barrier();      // scatter complete everywhere

    // ---- Phase 3: pruned NN search -----------------------------------------
    const int dir = blockIdx.x >> 6;                // 64 CTAs per direction
    const int si  = (blockIdx.x & 63) * TPB + tid;  // sorted index -> z-coherent warps

    const float4 a = g_sorted[dir][si];
    const float sx = -0.5f * a.x;
    const float sy = -0.5f * a.y;
    const float sz = -0.5f * a.z;
    const float sn = a.w;
    const float zs = sz;

    const float4* __restrict__ T4 = g_sorted[dir ^ 1];
    const int* bs = sh_bs[dir ^ 1];

    float m = 3.4e38f;
    int b0 = zbin(zs);
    scan_range(T4, bs[b0], bs[b0 + 1], sx, sy, sz, m);
    int lo = b0, hi = b0 + 1;

    while (true) {
        float dlo = (lo > 0)     ? (zs - (ZMIN + (float)lo * DZ)) : 1e30f;
        float dhi = (hi < NBINS) ? ((ZMIN + (float)hi * DZ) - zs) : 1e30f;
        float g = fminf(dlo, dhi);
        if (sn + m <= g * g) break;     // unscanned bins are >= g away in z
        if (dlo < dhi) { lo--; scan_range(T4, bs[lo], bs[lo + 1], sx, sy, sz, m); }
        else           { scan_range(T4, bs[hi], bs[hi + 1], sx, sy, sz, m); hi++; }
    }

    // ---- Phase 4: reduce + last-block finalize -----------------------------
    red[tid] = m + sn;                  // = min_j ||s_i - t_j||^2
    __syncthreads();
    for (int s = TPB / 2; s > 0; s >>= 1) {
        if (tid < s) red[tid] += red[tid + s];
        __syncthreads();
    }
    if (tid == 0) {
        atomicAdd(&g_sum, red[0]);
        if (atom_add_acqrel(&g_done, 1u) == GRID - 1) {
            float total = atomicExch(&g_sum, 0.0f);
            out[0] = total / (float)(2 * NPTS);     // (mean_pt + mean_tp)/2
            g_done = 0;
            // Reset scratch for the next replay (all reads of these are done).
            for (int k = 0; k < 2 * NBINS; k++) {
                ((int*)g_hist)[k]   = 0;
                ((int*)g_cursor)[k] = 0;
            }
        }
    }
}

extern "C" void kernel_launch(void* const* d_in, const int* in_sizes, int n_in,
                              void* d_out, int out_size)
{
    const float* pred = (const float*)d_in[0];
    const float* tgt  = (const float*)d_in[1];
    float* out = (float*)d_out;

    chamfer_fused<<<GRID, TPB>>>(pred, tgt, out);
}

// round 8
// speedup vs baseline: 1.6988x; 1.6988x over previous
#include <cuda_runtime.h>
#include <cstdint>

#define NPTS   16384
#define NBINS  256
#define CAP    512                 // padded slots per bin (mean ~307, +12 sigma)
#define ZMIN   (-6.0f)
#define DZ     (12.0f / 256.0f)
#define INV_DZ (256.0f / 12.0f)
#define GRID   128
#define TPB    1024                // 4 roles per point

// Zero-initialized at load; finalizer resets what must be zero per replay.
// Barrier state (g_arrive, g_flag) is monotonic -> replay-safe, never reset.
__device__ int      g_cursor[2][NBINS];
__device__ float4   g_bins[2][NBINS * CAP];  // (-2x,-2y,-2z,|p|^2)
__device__ float    g_sum;
__device__ unsigned g_done;
__device__ unsigned g_arrive;
__device__ unsigned g_flag[GRID];

__device__ __forceinline__ int zbin(float z) {
    int b = (int)floorf((z - ZMIN) * INV_DZ);
    return max(0, min(NBINS - 1, b));
}

// ---- L2-coherent primitives ------------------------------------------------
__device__ __forceinline__ unsigned ld_acq(unsigned* p) {
    unsigned v;
    asm volatile("ld.acquire.gpu.global.u32 %0, [%1];" : "=r"(v) : "l"(p) : "memory");
    return v;
}
__device__ __forceinline__ void st_rel(unsigned* p, unsigned v) {
    asm volatile("st.release.gpu.global.u32 [%0], %1;" :: "l"(p), "r"(v) : "memory");
}
__device__ __forceinline__ unsigned atom_add_rel(unsigned* p, unsigned v) {
    unsigned o;
    asm volatile("atom.add.release.gpu.global.u32 %0, [%1], %2;"
                 : "=r"(o) : "l"(p), "r"(v) : "memory");
    return o;
}
__device__ __forceinline__ unsigned atom_add_acqrel(unsigned* p, unsigned v) {
    unsigned o;
    asm volatile("atom.add.acq_rel.gpu.global.u32 %0, [%1], %2;"
                 : "=r"(o) : "l"(p), "r"(v) : "memory");
    return o;
}

// Distributed-release grid barrier: waiters each poll their OWN flag line, so
// the releaser's stores never fight a 127-reader storm on one L2 line.
// GRID=128 <= 148 SMs -> all CTAs co-resident in wave 1.
__device__ __forceinline__ void grid_barrier() {
    __syncthreads();
    if (threadIdx.x == 0) {
        // Pre-arrive read of my own flag is stable: release can't happen
        // before my arrive. Flags move in lockstep, one bump per barrier.
        unsigned my = ld_acq(&g_flag[blockIdx.x]);
        __threadfence();                       // publish this CTA's writes
        unsigned old = atom_add_rel(&g_arrive, 1u);   // monotonic, no reset
        if ((old + 1u) % GRID == 0u) {
            #pragma unroll 4
            for (int c = 0; c < GRID; c++) st_rel(&g_flag[c], my + 1u);
        } else {
            while (ld_acq(&g_flag[blockIdx.x]) == my) __nanosleep(128);
        }
    }
    __syncthreads();
}

// ---- role-strided scan of one padded bin ----------------------------------
__device__ __forceinline__ void scan_bin_role(const float4* __restrict__ T,
                                              int jb, int je, int role,
                                              float sx, float sy, float sz,
                                              float& m) {
    float ma = 3.4e38f, mb = 3.4e38f;
    int j = jb + role;
    for (; j + 4 < je; j += 8) {               // 2 outstanding loads per role
        float4 ta = T[j];
        float4 tb = T[j + 4];
        float da = fmaf(sx, ta.x, ta.w);
        float db = fmaf(sx, tb.x, tb.w);
        da = fmaf(sy, ta.y, da);
        db = fmaf(sy, tb.y, db);
        da = fmaf(sz, ta.z, da);
        db = fmaf(sz, tb.z, db);
        ma = fminf(ma, da);
        mb = fminf(mb, db);
    }
    if (j < je) {
        float4 ta = T[j];
        float da = fmaf(sx, ta.x, ta.w);
        da = fmaf(sy, ta.y, da);
        da = fmaf(sz, ta.z, da);
        ma = fminf(ma, da);
    }
    m = fminf(m, fminf(ma, mb));
}

__global__ void __launch_bounds__(TPB, 1) chamfer_fused(
    const float* __restrict__ pred, const float* __restrict__ tgt,
    float* __restrict__ out)
{
    __shared__ int   sh_cnt[2 * NBINS];
    __shared__ float red[TPB];

    const int tid  = threadIdx.x;
    const int role = tid & 3;

    // ---- Phase A: scatter into fixed-capacity padded bins (no histogram) ---
    const int grp  = blockIdx.x * (TPB / 4) + (tid >> 2);   // 0..32767
    const int pdir = grp >> 14;
    const int pi   = grp & (NPTS - 1);
    const float* __restrict__ P = pdir ? tgt : pred;
    const float px = P[3 * pi + 0];          // 4 roles load same point: L1 broadcast
    const float py = P[3 * pi + 1];
    const float pz = P[3 * pi + 2];
    const float sn = px * px + py * py + pz * pz;
    const int  pbin = zbin(pz);
    if (role == 0) {
        const int slot = atomicAdd(&g_cursor[pdir][pbin], 1);
        g_bins[pdir][(pbin << 9) + slot] =
            make_float4(-2.0f * px, -2.0f * py, -2.0f * pz, sn);
    }

    grid_barrier();    // the ONLY device-wide sync

    // ---- bin counts into smem ----------------------------------------------
    if (tid < 2 * NBINS) sh_cnt[tid] = ((int*)g_cursor)[tid];
    __syncthreads();

    // ---- Phase B: pruned NN search, 4 roles per point ----------------------
    const int dirT = pdir ^ 1;
    const float4* __restrict__ T = g_bins[dirT];
    const int* cnt = &sh_cnt[dirT * NBINS];
    const float sx = px, sy = py, sz = pz;     // plain coords; T holds -2*t
    const float zs = pz;
    const unsigned gmask = 0xFu << ((tid & 31) & ~3);   // my 4-lane role group

    float m = 3.4e38f;
    int b0 = zbin(zs);
    scan_bin_role(T, b0 << 9, (b0 << 9) + cnt[b0], role, sx, sy, sz, m);
    m = fminf(m, __shfl_xor_sync(gmask, m, 1));
    m = fminf(m, __shfl_xor_sync(gmask, m, 2));
    int lo = b0, hi = b0 + 1;

    while (true) {
        float dlo = (lo > 0)     ? (zs - (ZMIN + (float)lo * DZ)) : 1e30f;
        float dhi = (hi < NBINS) ? ((ZMIN + (float)hi * DZ) - zs) : 1e30f;
        float g = fminf(dlo, dhi);
        if (sn + m <= g * g) break;    // all unscanned points are >= g away in z
        int b;
        if (dlo < dhi) { lo--; b = lo; }
        else           { b = hi; hi++; }
        scan_bin_role(T, b << 9, (b << 9) + cnt[b], role, sx, sy, sz, m);
        m = fminf(m, __shfl_xor_sync(gmask, m, 1));
        m = fminf(m, __shfl_xor_sync(gmask, m, 2));
    }

    // ---- Phase C: reduce + last-block finalize -----------------------------
    red[tid] = (role == 0) ? (m + sn) : 0.0f;  // = min_j ||s_i - t_j||^2
    __syncthreads();
    for (int s = TPB / 2; s > 0; s >>= 1) {
        if (tid < s) red[tid] += red[tid + s];
        __syncthreads();
    }
    if (tid == 0) {
        atomicAdd(&g_sum, red[0]);
        if ((atom_add_acqrel(&g_done, 1u) + 1u) % GRID == 0u) {
            float total = atomicExch(&g_sum, 0.0f);
            out[0] = total / (float)(2 * NPTS);   // (mean_pt + mean_tp)/2
            // Reset cursors for the next graph replay (all readers are done).
            for (int k = 0; k < 2 * NBINS; k++) ((int*)g_cursor)[k] = 0;
        }
    }
}

extern "C" void kernel_launch(void* const* d_in, const int* in_sizes, int n_in,
                              void* d_out, int out_size)
{
    const float* pred = (const float*)d_in[0];
    const float* tgt  = (const float*)d_in[1];
    float* out = (float*)d_out;

    chamfer_fused<<<GRID, TPB>>>(pred, tgt, out);
}